// round 15
// baseline (speedup 1.0000x reference)
#include <cuda_runtime.h>
#include <cstdint>

#define BB 16384
#define EE 64
#define DD 128
#define ES 3
#define NBLK (BB / 64)          // 256 route blocks
#define GRID 296                // 2 CTAs/SM x 148 SMs, all co-resident
#define NT 512
#define NTASK_A (NBLK + EE)     // 256 route + 64 wt tasks
#define ECHUNK 4
#define NTASK_E (BB / ECHUNK)

typedef unsigned long long ull;
typedef long long ll;

// ---------------- device scratch (static; no allocations allowed) -------------
__device__ int    g_offsets[EE + 1];
__device__ int    g_ntiles;
__device__ int    g_picked[BB * ES];
__device__ int    g_loc[BB * ES];
__device__ float  g_w[BB * ES];
__device__ int    g_entry_token[BB * ES];
__device__ int    g_pos[BB * ES];
__device__ int2   g_tiles[1024];
__device__ int    g_blockhist[NBLK * EE];
__device__ int    g_blockbase[NBLK * EE];
__device__ float  g_wt[(size_t)EE * DD * DD];        // tf32-rounded W^T [e][o][k]
__device__ float  g_scratch[(size_t)BB * ES * DD];   // 25 MB

// work-stealing counters (reset at end of every launch -> replay-safe)
__device__ int g_task_a = 0;
__device__ int g_task_d = 0;
__device__ int g_task_e = 0;

// ---------------- grid barrier (sense-reversing, replay-safe) ------------------
__device__ int          g_bar_count = 0;
__device__ volatile int g_bar_gen   = 0;

__device__ __forceinline__ void grid_sync() {
    __syncthreads();
    if (threadIdx.x == 0) {
        __threadfence();
        int gen = g_bar_gen;
        if (atomicAdd(&g_bar_count, 1) == GRID - 1) {
            g_bar_count = 0;
            __threadfence();
            g_bar_gen = gen + 1;
        } else {
            while (g_bar_gen == gen) __nanosleep(32);
        }
        __threadfence();
    }
    __syncthreads();
}

// ---------------- helpers ------------------------------------------------------
__device__ __forceinline__ ull pack2(float lo, float hi) {
    ull r;
    asm("mov.b64 %0, {%1, %2};" : "=l"(r) : "f"(lo), "f"(hi));
    return r;
}
__device__ __forceinline__ float2 unpack2(ull v) {
    float2 f;
    asm("mov.b64 {%0, %1}, %2;" : "=f"(f.x), "=f"(f.y) : "l"(v));
    return f;
}
__device__ __forceinline__ ull fma2(ull a, ull b, ull c) {
    ull d;
    asm("fma.rn.f32x2 %0, %1, %2, %3;" : "=l"(d) : "l"(a), "l"(b), "l"(c));
    return d;
}
__device__ __forceinline__ ull add2(ull a, ull b) {
    ull d;
    asm("add.rn.f32x2 %0, %1, %2;" : "=l"(d) : "l"(a), "l"(b));
    return d;
}
__device__ __forceinline__ float to_tf32(float x) {
    float r;
    asm("cvt.rna.tf32.f32 %0, %1;" : "=f"(r) : "f"(x));
    return r;
}
__device__ __forceinline__ void mma_tf32(float* c, const uint32_t* a,
                                         const uint32_t* b) {
    asm volatile(
        "mma.sync.aligned.m16n8k8.row.col.f32.tf32.tf32.f32 "
        "{%0,%1,%2,%3}, {%4,%5,%6,%7}, {%8,%9}, {%0,%1,%2,%3};"
        : "+f"(c[0]), "+f"(c[1]), "+f"(c[2]), "+f"(c[3])
        : "r"(a[0]), "r"(a[1]), "r"(a[2]), "r"(a[3]), "r"(b[0]), "r"(b[1]));
}
__device__ __forceinline__ void cp_async16(uint32_t dst, const void* src) {
    asm volatile("cp.async.cg.shared.global [%0], [%1], 16;"
                 :: "r"(dst), "l"(src) : "memory");
}
#define CP_COMMIT() asm volatile("cp.async.commit_group;" ::: "memory")
#define CP_WAIT0()  asm volatile("cp.async.wait_group 0;" ::: "memory")

// smem layout sizes
#define K1_XA 132               // token-major x tile leading dim (33x16B -> conflict-free)
#define K1_CP 36
#define K1_TP 36
#define K4_LD 132
// GEMM: A[64][132] + B[128][132] = 101376 B (dominates routing's ~62KB)
#define FUSED_SMEM ((64 * K4_LD + 128 * K4_LD) * 4 + 128)

// ---------------- fused persistent kernel --------------------------------------
__global__ __launch_bounds__(NT, 2) void fused(const float* __restrict__ x,
                                               const float* __restrict__ dscale,
                                               const float* __restrict__ cent,
                                               const float* __restrict__ W,
                                               const float* __restrict__ bias,
                                               float* __restrict__ out) {
    extern __shared__ float sm[];
    __shared__ int s_task;
    int tid = threadIdx.x;
    int cta = blockIdx.x;

    // ================= Phase A: work-stealing over {route blocks, W^T} =========
    {
        float*  xs   = sm;                          // [64][K1_XA]  token-major!
        float*  cs   = xs + 64 * K1_XA;             // [128][K1_CP] k-major
        float*  ts   = cs + 128 * K1_CP;            // [64][K1_TP]
        double* nc2s = (double*)(ts + 64 * K1_TP);  // [32]
        int*    hist = (int*)(nc2s + 32);           // [64]
        double* nx2s = (double*)(hist + 64);        // [64]
        const float4* x4 = (const float4*)x;
        const float4* c4 = (const float4*)cent;

        for (;;) {
            if (tid == 0) s_task = atomicAdd(&g_task_a, 1);
            __syncthreads();
            int task = s_task;
            __syncthreads();
            if (task >= NTASK_A) break;

            if (task < NBLK) {
                // -------- route block --------
                int t0 = task * 64;
                if (tid < 64) hist[tid] = 0;
                // x tile: token-major direct float4 stores (2048 f4, 4/thread)
#pragma unroll
                for (int i = 0; i < 4; i++) {
                    int f = i * NT + tid;
                    int tr = f & 63, kc = f >> 6;
                    float4 v = __ldg(x4 + (size_t)(t0 + tr) * 32 + kc);
                    *(float4*)(xs + tr * K1_XA + kc * 4) = v;
                }
                // centroids: k-major transposed (1024 f4, 2/thread)
#pragma unroll
                for (int i = 0; i < 2; i++) {
                    int f = i * NT + tid;
                    int er = f & 31, kc = f >> 5;
                    float4 v = __ldg(c4 + (size_t)er * 32 + kc);
                    cs[(kc * 4 + 0) * K1_CP + er] = v.x;
                    cs[(kc * 4 + 1) * K1_CP + er] = v.y;
                    cs[(kc * 4 + 2) * K1_CP + er] = v.z;
                    cs[(kc * 4 + 3) * K1_CP + er] = v.w;
                }
                __syncthreads();

                // centroid norms (fp64), warp 0 — overlaps with dots below
                if (tid < 32) {
                    double a0 = 0.0, a1 = 0.0;
#pragma unroll 8
                    for (int k = 0; k < 128; k += 2) {
                        double u0 = (double)cs[(k + 0) * K1_CP + tid]; a0 = fma(u0, u0, a0);
                        double u1 = (double)cs[(k + 1) * K1_CP + tid]; a1 = fma(u1, u1, a1);
                    }
                    nc2s[tid] = a0 + a1;
                }

                // dots: ALL 512 threads, 1 token x 4 experts each.
                // Same per-(token,quad) accumulation order as before -> ts bits identical.
                {
                    int tx = tid & 7, tok = tid >> 3;
                    ull acc[2][4];
#pragma unroll
                    for (int j = 0; j < 2; j++)
#pragma unroll
                        for (int s = 0; s < 4; s++) acc[j][s] = 0ULL;

                    const float* ap = xs + tok * K1_XA;
                    const float* bp = cs + tx * 4;
#pragma unroll 4
                    for (int k = 0; k < 128; k += 4) {
                        float4 a = *(const float4*)(ap + k);
                        float  as4[4] = {a.x, a.y, a.z, a.w};
#pragma unroll
                        for (int s = 0; s < 4; s++) {
                            double2 nb = *(const double2*)(bp + (k + s) * K1_CP);
                            ull b01 = __double_as_longlong(nb.x);
                            ull b23 = __double_as_longlong(nb.y);
                            ull a0 = pack2(as4[s], as4[s]);
                            acc[0][s] = fma2(a0, b01, acc[0][s]);
                            acc[1][s] = fma2(a0, b23, acc[1][s]);
                        }
                    }
                    ull s01 = add2(add2(acc[0][0], acc[0][1]),
                                   add2(acc[0][2], acc[0][3]));
                    ull s23 = add2(add2(acc[1][0], acc[1][1]),
                                   add2(acc[1][2], acc[1][3]));
                    float2 v01 = unpack2(s01), v23 = unpack2(s23);
                    *(float4*)(ts + tok * K1_TP + tx * 4) =
                        make_float4(v01.x, v01.y, v23.x, v23.y);
                }
                __syncthreads();

                // |x|^2 fp64: 2 threads/token, bit-exact combine (a0+a1)+(a2+a3)
                if (tid < 128) {
                    int tok = tid >> 1, side = tid & 1;
                    const float* xr = xs + tok * K1_XA;
                    double a0 = 0.0, a1 = 0.0;
                    int base = side * 2;
#pragma unroll 8
                    for (int k = 0; k < 128; k += 4) {
                        double u0 = (double)xr[k + base + 0]; a0 = fma(u0, u0, a0);
                        double u1 = (double)xr[k + base + 1]; a1 = fma(u1, u1, a1);
                    }
                    double h = a0 + a1;                    // side0: a0+a1, side1: a2+a3
                    double hp = __shfl_down_sync(0xFFFFFFFFu, h, 1);
                    if (side == 0) nx2s[tok] = h + hp;     // (a0+a1)+(a2+a3)
                }
                __syncthreads();

                // ranking: 2 threads/token, int64 compares (order-isomorphic)
                if (tid < 128) {
                    int tok = tid >> 1, side = tid & 1;
                    double nx2 = nx2s[tok];
                    float  s  = __ldg(dscale);
                    double Kd = ((double)s * (double)s) * (1.0 / 128.0);

                    ll av[3] = {0x7FF0000000000000LL, 0x7FF0000000000000LL,
                                0x7FF0000000000000LL};
                    int ai[3] = {0, 0, 0};
                    for (int ei = 0; ei < 32; ei++) {
                        double t  = (double)ts[tok * K1_TP + ei];
                        double br = nx2 + nc2s[ei];
                        double dd = Kd * (side == 0 ? fma(-2.0, t, br)
                                                    : fma(2.0, t, br));
                        ll db = __double_as_longlong(dd);
                        int e = side * 32 + ei;
                        if (db < av[0]) {
                            av[2] = av[1]; ai[2] = ai[1];
                            av[1] = av[0]; ai[1] = ai[0];
                            av[0] = db;    ai[0] = e;
                        } else if (db < av[1]) {
                            av[2] = av[1]; ai[2] = ai[1];
                            av[1] = db;    ai[1] = e;
                        } else if (db < av[2]) {
                            av[2] = db;    ai[2] = e;
                        }
                    }
                    ll  bv[3];
                    int bi[3];
#pragma unroll
                    for (int r = 0; r < 3; r++) {
                        bv[r] = __shfl_down_sync(0xFFFFFFFFu, av[r], 1);
                        bi[r] = __shfl_down_sync(0xFFFFFFFFu, ai[r], 1);
                    }
                    if (side == 0) {
                        int ri[3]; int pa = 0, pb = 0;
#pragma unroll
                        for (int r = 0; r < 3; r++) {
                            bool takeB = (pa > 2) || (pb <= 2 && bv[pb] < av[pa]);
                            if (takeB) { ri[r] = bi[pb]; pb++; }
                            else       { ri[r] = ai[pa]; pa++; }
                        }
                        float d0 = (float)(Kd * fma(-2.0, (double)ts[tok * K1_TP + 0], nx2 + nc2s[0]));
                        float d1 = (float)(Kd * fma(-2.0, (double)ts[tok * K1_TP + 1], nx2 + nc2s[1]));
                        float d2 = (float)(Kd * fma(-2.0, (double)ts[tok * K1_TP + 2], nx2 + nc2s[2]));
                        float w0 = 1.0f / (1.0f + d0);
                        float w1 = 1.0f / (1.0f + d1);
                        float w2 = 1.0f / (1.0f + d2);
                        float z  = w0 + w1 + w2;
                        int b = t0 + tok;
                        g_picked[b * 3 + 0] = ri[0];
                        g_picked[b * 3 + 1] = ri[1];
                        g_picked[b * 3 + 2] = ri[2];
                        g_w[b * 3 + 0] = w0 / z;
                        g_w[b * 3 + 1] = w1 / z;
                        g_w[b * 3 + 2] = w2 / z;
                        g_loc[b * 3 + 0] = atomicAdd(&hist[ri[0]], 1);
                        g_loc[b * 3 + 1] = atomicAdd(&hist[ri[1]], 1);
                        g_loc[b * 3 + 2] = atomicAdd(&hist[ri[2]], 1);
                    }
                }
                __syncthreads();
                if (tid < 64) g_blockhist[task * 64 + tid] = hist[tid];
                __syncthreads();
            } else {
                // -------- W^T build for expert e --------
                int e = task - NBLK;
                float* wsm = sm;                     // [128][132] wsm[k][o]
                const float4* w4 = (const float4*)(W + (size_t)e * DD * DD);
#pragma unroll
                for (int i = 0; i < 8; i++) {
                    int idx = i * NT + tid;
                    float4 v = __ldg(w4 + idx);
                    *(float4*)(wsm + (idx >> 5) * 132 + (idx & 31) * 4) = v;
                }
                __syncthreads();
                float4* dst = (float4*)(g_wt + (size_t)e * DD * DD);
#pragma unroll
                for (int i = 0; i < 8; i++) {
                    int idx = i * NT + tid;
                    int o = idx >> 5, kq = idx & 31;
                    float4 v;
                    v.x = to_tf32(wsm[(kq * 4 + 0) * 132 + o]);
                    v.y = to_tf32(wsm[(kq * 4 + 1) * 132 + o]);
                    v.z = to_tf32(wsm[(kq * 4 + 2) * 132 + o]);
                    v.w = to_tf32(wsm[(kq * 4 + 3) * 132 + o]);
                    dst[o * 32 + kq] = v;
                }
                __syncthreads();
            }
        }
    }

    grid_sync();

    // ================= Phase B: scan (CTA 0) ===================================
    if (cta == 0) {
        int* csum = (int*)sm;        // [256]
        int* cnts = csum + 256;      // [64]
        int* off  = cnts + 64;       // [65]
        int* toff = off + 65;        // [64]
        int e = tid & 63, c = (tid >> 6) & 3;

        if (tid < 256) {
            int s = 0;
#pragma unroll 8
            for (int i = 0; i < 64; i++) s += g_blockhist[((c << 6) + i) * 64 + e];
            csum[c * 64 + e] = s;
        }
        __syncthreads();

        if (tid < 64) {
            int t0 = csum[0 * 64 + tid], t1 = csum[1 * 64 + tid];
            int t2 = csum[2 * 64 + tid], t3 = csum[3 * 64 + tid];
            cnts[tid] = t0 + t1 + t2 + t3;
            csum[0 * 64 + tid] = 0;
            csum[1 * 64 + tid] = t0;
            csum[2 * 64 + tid] = t0 + t1;
            csum[3 * 64 + tid] = t0 + t1 + t2;
        }
        __syncthreads();

        if (tid == 0) {
            int o = 0, to = 0;
            for (int i = 0; i < 64; i++) {
                off[i] = o; toff[i] = to;
                o += cnts[i]; to += (cnts[i] + 63) >> 6;
            }
            off[64] = o; g_ntiles = to;
        }
        __syncthreads();

        if (tid < 64) {
            g_offsets[tid] = off[tid];
            int nt = (cnts[tid] + 63) >> 6;
            for (int i = 0; i < nt; i++)
                g_tiles[toff[tid] + i] = make_int2(tid, off[tid] + (i << 6));
        }
        if (tid == 0) g_offsets[64] = off[64];
        __syncthreads();

        if (tid < 256) {
            int run = off[e] + csum[c * 64 + e];
            for (int i = 0; i < 64; i++) {
                int idx = ((c << 6) + i) * 64 + e;
                int v = g_blockhist[idx];
                g_blockbase[idx] = run;
                run += v;
            }
        }
    }

    grid_sync();

    // ================= Phase C: scatter ========================================
    {
        int t = cta * NT + tid;
        if (t < BB) {
            int blk = t >> 6;
#pragma unroll
            for (int j = 0; j < 3; j++) {
                int e = g_picked[t * 3 + j];
                int p = g_blockbase[blk * 64 + e] + g_loc[t * 3 + j];
                g_entry_token[p] = t;
                g_pos[t * 3 + j] = p;
            }
        }
    }

    grid_sync();

    // ================= Phase D: TF32 grouped GEMM, work-stealing ===============
    {
        float* As = sm;                  // [64][K4_LD]
        float* Bs = sm + 64 * K4_LD;     // [128][K4_LD]
        uint32_t bsb = (uint32_t)__cvta_generic_to_shared(Bs);
        int ntiles = g_ntiles;
        const float4* x4 = (const float4*)x;

        for (;;) {
            if (tid == 0) s_task = atomicAdd(&g_task_d, 1);
            __syncthreads();
            int t = s_task;
            __syncthreads();
            if (t >= ntiles) break;

            int2 tl = g_tiles[t];
            int e = tl.x, rs = tl.y;
            int rows = g_offsets[e + 1] - rs;
            if (rows > 64) rows = 64;

            // B: cp.async copy of pre-rounded W^T (4096 float4)
            const float4* wt4 = (const float4*)(g_wt + (size_t)e * DD * DD);
#pragma unroll
            for (int i = 0; i < 8; i++) {
                int idx = i * NT + tid;
                int o = idx >> 5, kq = idx & 31;
                cp_async16(bsb + (o * K4_LD + kq * 4) * 4, wt4 + idx);
            }
            CP_COMMIT();

            // A: gather + tf32 round + STS (8 threads per row)
            {
                int tr = tid >> 3, h = tid & 7;
                bool valid = tr < rows;
                int tok = valid ? g_entry_token[rs + tr] : 0;
                const float4* xr = x4 + (size_t)tok * 32;
#pragma unroll
                for (int i = 0; i < 4; i++) {
                    int kc = h * 4 + i;
                    float4 v = make_float4(0.f, 0.f, 0.f, 0.f);
                    if (valid) v = __ldg(xr + kc);
                    v.x = to_tf32(v.x); v.y = to_tf32(v.y);
                    v.z = to_tf32(v.z); v.w = to_tf32(v.w);
                    *(float4*)(As + tr * K4_LD + kc * 4) = v;
                }
            }
            CP_WAIT0();
            __syncthreads();

            int wid = tid >> 5, lane = tid & 31;
            int gid = lane >> 2, tig = lane & 3;
            int m0 = (wid & 3) * 16, n0 = (wid >> 2) * 32;

            float acc[4][4];
#pragma unroll
            for (int j = 0; j < 4; j++)
#pragma unroll
                for (int r = 0; r < 4; r++) acc[j][r] = 0.f;

            const float* arow = As + (m0 + gid) * K4_LD + tig;
            const float* brow = Bs + (n0 + gid) * K4_LD + tig;

#pragma unroll 4
            for (int kb = 0; kb < 128; kb += 8) {
                uint32_t a[4];
                {
                    const float* p = arow + kb;
                    a[0] = __float_as_uint(p[0]);
                    a[1] = __float_as_uint(p[8 * K4_LD]);
                    a[2] = __float_as_uint(p[4]);
                    a[3] = __float_as_uint(p[8 * K4_LD + 4]);
                }
                uint32_t b[4][2];
#pragma unroll
                for (int j = 0; j < 4; j++) {
                    const float* p = brow + j * 8 * K4_LD + kb;
                    b[j][0] = __float_as_uint(p[0]);
                    b[j][1] = __float_as_uint(p[4]);
                }
#pragma unroll
                for (int j = 0; j < 4; j++)
                    mma_tf32(acc[j], a, b[j]);
            }

            const float* be = bias + (size_t)e * DD;
            {
                int r0 = m0 + gid;
                int r1 = r0 + 8;
                bool v0 = r0 < rows, v1 = r1 < rows;
                float* o0 = g_scratch + (size_t)(rs + r0) * DD;
                float* o1 = g_scratch + (size_t)(rs + r1) * DD;
#pragma unroll
                for (int j = 0; j < 4; j++) {
                    int col = n0 + j * 8 + tig * 2;
                    float2 bv = *(const float2*)(be + col);
                    if (v0) *(float2*)(o0 + col) =
                        make_float2(acc[j][0] + bv.x, acc[j][1] + bv.y);
                    if (v1) *(float2*)(o1 + col) =
                        make_float2(acc[j][2] + bv.x, acc[j][3] + bv.y);
                }
            }
        }
    }

    grid_sync();

    // ================= Phase E: weighted combine, per-warp stealing ============
    {
        int lane = tid & 31;
        int c = lane * 4;
        for (;;) {
            int ch;
            if (lane == 0) ch = atomicAdd(&g_task_e, 1);
            ch = __shfl_sync(0xFFFFFFFFu, ch, 0);
            if (ch >= NTASK_E) break;
            int b0 = ch * ECHUNK;
#pragma unroll
            for (int b = b0; b < b0 + ECHUNK; b++) {
                float4 r = make_float4(0.f, 0.f, 0.f, 0.f);
#pragma unroll
                for (int j = 0; j < 3; j++) {
                    float w = g_w[b * 3 + j];
                    int   p = g_pos[b * 3 + j];
                    float4 sv = *(const float4*)(g_scratch + (size_t)p * DD + c);
                    r.x += w * sv.x;
                    r.y += w * sv.y;
                    r.z += w * sv.z;
                    r.w += w * sv.w;
                }
                *(float4*)(out + (size_t)b * DD + c) = r;
            }
        }
    }

    grid_sync();   // all stealing done -> safe to reset counters for next replay
    if (cta == 0 && tid == 0) {
        g_task_a = 0;
        g_task_d = 0;
        g_task_e = 0;
    }
}

// ---------------- launch ------------------------------------------------------
extern "C" void kernel_launch(void* const* d_in, const int* in_sizes, int n_in,
                              void* d_out, int out_size) {
    const float* x    = (const float*)d_in[0];
    const float* dsc  = (const float*)d_in[1];
    const float* cent = (const float*)d_in[2];
    const float* W    = (const float*)d_in[3];
    const float* bias = (const float*)d_in[4];
    float* out = (float*)d_out;

    cudaFuncSetAttribute(fused, cudaFuncAttributeMaxDynamicSharedMemorySize,
                         FUSED_SMEM);
    fused<<<GRID, NT, FUSED_SMEM>>>(x, dsc, cent, W, bias, out);
}

// round 17
// speedup vs baseline: 1.1140x; 1.1140x over previous
#include <cuda_runtime.h>
#include <cstdint>

#define BB 16384
#define EE 64
#define DD 128
#define ES 3
#define NBLK (BB / 64)          // 256 route blocks
#define GRID 296                // 2 CTAs/SM x 148 SMs, all co-resident
#define NT 512
#define NTASK_A (NBLK + EE)     // 256 route + 64 wt tasks

typedef unsigned long long ull;
typedef long long ll;

// ---------------- device scratch (static; no allocations allowed) -------------
__device__ int    g_offsets[EE + 1];
__device__ int    g_ntiles;
__device__ int    g_picked[BB * ES];
__device__ int    g_loc[BB * ES];
__device__ float  g_w[BB * ES];
__device__ int    g_entry_token[BB * ES];
__device__ int    g_pos[BB * ES];
__device__ int2   g_tiles[1024];
__device__ int    g_blockhist[NBLK * EE];
__device__ int    g_blockbase[NBLK * EE];
__device__ float  g_wt[(size_t)EE * DD * DD];        // tf32-rounded W^T [e][o][k]
__device__ float  g_scratch[(size_t)BB * ES * DD];   // 25 MB

// work-stealing counters (reset in dead phases -> replay-safe, no extra barrier)
__device__ int g_task_a = 0;
__device__ int g_task_d = 0;

// ---------------- grid barrier (sense-reversing, replay-safe) ------------------
__device__ int          g_bar_count = 0;
__device__ volatile int g_bar_gen   = 0;

__device__ __forceinline__ void grid_sync() {
    __syncthreads();
    if (threadIdx.x == 0) {
        __threadfence();
        int gen = g_bar_gen;
        if (atomicAdd(&g_bar_count, 1) == GRID - 1) {
            g_bar_count = 0;
            __threadfence();
            g_bar_gen = gen + 1;
        } else {
            while (g_bar_gen == gen) __nanosleep(32);
        }
        __threadfence();
    }
    __syncthreads();
}

// ---------------- helpers ------------------------------------------------------
__device__ __forceinline__ ull pack2(float lo, float hi) {
    ull r;
    asm("mov.b64 %0, {%1, %2};" : "=l"(r) : "f"(lo), "f"(hi));
    return r;
}
__device__ __forceinline__ float2 unpack2(ull v) {
    float2 f;
    asm("mov.b64 {%0, %1}, %2;" : "=f"(f.x), "=f"(f.y) : "l"(v));
    return f;
}
__device__ __forceinline__ ull fma2(ull a, ull b, ull c) {
    ull d;
    asm("fma.rn.f32x2 %0, %1, %2, %3;" : "=l"(d) : "l"(a), "l"(b), "l"(c));
    return d;
}
__device__ __forceinline__ ull add2(ull a, ull b) {
    ull d;
    asm("add.rn.f32x2 %0, %1, %2;" : "=l"(d) : "l"(a), "l"(b));
    return d;
}
__device__ __forceinline__ float to_tf32(float x) {
    float r;
    asm("cvt.rna.tf32.f32 %0, %1;" : "=f"(r) : "f"(x));
    return r;
}
__device__ __forceinline__ void mma_tf32(float* c, const uint32_t* a,
                                         const uint32_t* b) {
    asm volatile(
        "mma.sync.aligned.m16n8k8.row.col.f32.tf32.tf32.f32 "
        "{%0,%1,%2,%3}, {%4,%5,%6,%7}, {%8,%9}, {%0,%1,%2,%3};"
        : "+f"(c[0]), "+f"(c[1]), "+f"(c[2]), "+f"(c[3])
        : "r"(a[0]), "r"(a[1]), "r"(a[2]), "r"(a[3]), "r"(b[0]), "r"(b[1]));
}
__device__ __forceinline__ void cp_async16(uint32_t dst, const void* src) {
    asm volatile("cp.async.cg.shared.global [%0], [%1], 16;"
                 :: "r"(dst), "l"(src) : "memory");
}
#define CP_COMMIT() asm volatile("cp.async.commit_group;" ::: "memory")
#define CP_WAIT0()  asm volatile("cp.async.wait_group 0;" ::: "memory")

// smem layout sizes
#define K1_XP 68
#define K1_CP 36
#define K1_TP 36
#define K4_LD 132
// GEMM: A[64][132] + B[128][132] = 101376 B (dominates routing's ~64KB)
#define FUSED_SMEM ((64 * K4_LD + 128 * K4_LD) * 4 + 128)

// ---------------- fused persistent kernel --------------------------------------
__global__ __launch_bounds__(NT, 2) void fused(const float* __restrict__ x,
                                               const float* __restrict__ dscale,
                                               const float* __restrict__ cent,
                                               const float* __restrict__ W,
                                               const float* __restrict__ bias,
                                               float* __restrict__ out) {
    extern __shared__ float sm[];
    __shared__ int s_task;
    int tid = threadIdx.x;
    int cta = blockIdx.x;

    // ================= Phase A: work-stealing over {route blocks, W^T} =========
    {
        float*  xs   = sm;                          // [128][K1_XP]  k-major x^T
        float*  cs   = xs + 128 * K1_XP;            // [128][K1_CP]
        float*  ts   = cs + 128 * K1_CP;            // [64][K1_TP]
        double* nc2s = (double*)(ts + 64 * K1_TP);  // [32]
        int*    hist = (int*)(nc2s + 32);           // [64]
        double* nx2s = (double*)(hist + 64);        // [64]
        const float4* x4 = (const float4*)x;
        const float4* c4 = (const float4*)cent;

        for (;;) {
            if (tid == 0) s_task = atomicAdd(&g_task_a, 1);
            __syncthreads();
            int task = s_task;
            __syncthreads();
            if (task >= NTASK_A) break;

            if (task < NBLK) {
                // -------- route block --------
                int t0 = task * 64;
                if (tid < 64) hist[tid] = 0;
#pragma unroll
                for (int i = 0; i < 4; i++) {
                    int f = i * NT + tid;
                    int tr = f & 63, kc = f >> 6;
                    float4 v = __ldg(x4 + (size_t)(t0 + tr) * 32 + kc);
                    xs[(kc * 4 + 0) * K1_XP + tr] = v.x;
                    xs[(kc * 4 + 1) * K1_XP + tr] = v.y;
                    xs[(kc * 4 + 2) * K1_XP + tr] = v.z;
                    xs[(kc * 4 + 3) * K1_XP + tr] = v.w;
                }
#pragma unroll
                for (int i = 0; i < 2; i++) {
                    int f = i * NT + tid;
                    int er = f & 31, kc = f >> 5;
                    float4 v = __ldg(c4 + (size_t)er * 32 + kc);
                    cs[(kc * 4 + 0) * K1_CP + er] = v.x;
                    cs[(kc * 4 + 1) * K1_CP + er] = v.y;
                    cs[(kc * 4 + 2) * K1_CP + er] = v.z;
                    cs[(kc * 4 + 3) * K1_CP + er] = v.w;
                }
                __syncthreads();

                // centroid norms (fp64) on threads 320-351 (idle warps)
                if (tid >= 320 && tid < 352) {
                    int e = tid - 320;
                    double a0 = 0.0, a1 = 0.0;
#pragma unroll 8
                    for (int k = 0; k < 128; k += 2) {
                        double u0 = (double)cs[(k + 0) * K1_CP + e]; a0 = fma(u0, u0, a0);
                        double u1 = (double)cs[(k + 1) * K1_CP + e]; a1 = fma(u1, u1, a1);
                    }
                    nc2s[e] = a0 + a1;
                }

                // |x|^2 (fp64) on threads 256-319 (idle warps), 1 thread/token
                if (tid >= 256 && tid < 320) {
                    int tok = tid - 256;
                    double a0 = 0.0, a1 = 0.0, a2 = 0.0, a3 = 0.0;
#pragma unroll 8
                    for (int k = 0; k < 128; k += 4) {
                        double u0 = (double)xs[(k + 0) * K1_XP + tok]; a0 = fma(u0, u0, a0);
                        double u1 = (double)xs[(k + 1) * K1_XP + tok]; a1 = fma(u1, u1, a1);
                        double u2 = (double)xs[(k + 2) * K1_XP + tok]; a2 = fma(u2, u2, a2);
                        double u3 = (double)xs[(k + 3) * K1_XP + tok]; a3 = fma(u3, u3, a3);
                    }
                    nx2s[tok] = (a0 + a1) + (a2 + a3);
                }

                // dots (unchanged R14 mapping, threads 0..255 only)
                if (tid < 256) {
                    int tx = tid & 7, ty = tid >> 3;
                    ull acc[2][2][4];
#pragma unroll
                    for (int i = 0; i < 2; i++)
#pragma unroll
                        for (int j = 0; j < 2; j++)
#pragma unroll
                            for (int s = 0; s < 4; s++) acc[i][j][s] = 0ULL;

                    const float* ap = xs + ty * 2;
                    const float* bp = cs + tx * 4;
#pragma unroll 4
                    for (int k = 0; k < 128; k += 4) {
#pragma unroll
                        for (int s = 0; s < 4; s++) {
                            float2  a  = *(const float2*)(ap + (k + s) * K1_XP);
                            double2 nb = *(const double2*)(bp + (k + s) * K1_CP);
                            ull b01 = __double_as_longlong(nb.x);
                            ull b23 = __double_as_longlong(nb.y);
                            ull a0 = pack2(a.x, a.x), a1 = pack2(a.y, a.y);
                            acc[0][0][s] = fma2(a0, b01, acc[0][0][s]);
                            acc[0][1][s] = fma2(a0, b23, acc[0][1][s]);
                            acc[1][0][s] = fma2(a1, b01, acc[1][0][s]);
                            acc[1][1][s] = fma2(a1, b23, acc[1][1][s]);
                        }
                    }
#pragma unroll
                    for (int i = 0; i < 2; i++) {
                        ull s01 = add2(add2(acc[i][0][0], acc[i][0][1]),
                                       add2(acc[i][0][2], acc[i][0][3]));
                        ull s23 = add2(add2(acc[i][1][0], acc[i][1][1]),
                                       add2(acc[i][1][2], acc[i][1][3]));
                        float2 v01 = unpack2(s01), v23 = unpack2(s23);
                        int tok = ty * 2 + i;
                        *(float4*)(ts + tok * K1_TP + tx * 4) =
                            make_float4(v01.x, v01.y, v23.x, v23.y);
                    }
                }
                __syncthreads();

                // ranking: 2 threads/token, int64 compares (order-isomorphic)
                if (tid < 128) {
                    int tok = tid >> 1, side = tid & 1;
                    double nx2 = nx2s[tok];
                    float  s  = __ldg(dscale);
                    double Kd = ((double)s * (double)s) * (1.0 / 128.0);

                    ll av[3] = {0x7FF0000000000000LL, 0x7FF0000000000000LL,
                                0x7FF0000000000000LL};
                    int ai[3] = {0, 0, 0};
                    for (int ei = 0; ei < 32; ei++) {
                        double t  = (double)ts[tok * K1_TP + ei];
                        double br = nx2 + nc2s[ei];
                        double dd = Kd * (side == 0 ? fma(-2.0, t, br)
                                                    : fma(2.0, t, br));
                        ll db = __double_as_longlong(dd);
                        int e = side * 32 + ei;
                        if (db < av[0]) {
                            av[2] = av[1]; ai[2] = ai[1];
                            av[1] = av[0]; ai[1] = ai[0];
                            av[0] = db;    ai[0] = e;
                        } else if (db < av[1]) {
                            av[2] = av[1]; ai[2] = ai[1];
                            av[1] = db;    ai[1] = e;
                        } else if (db < av[2]) {
                            av[2] = db;    ai[2] = e;
                        }
                    }
                    ll  bv[3];
                    int bi[3];
#pragma unroll
                    for (int r = 0; r < 3; r++) {
                        bv[r] = __shfl_down_sync(0xFFFFFFFFu, av[r], 1);
                        bi[r] = __shfl_down_sync(0xFFFFFFFFu, ai[r], 1);
                    }
                    if (side == 0) {
                        int ri[3]; int pa = 0, pb = 0;
#pragma unroll
                        for (int r = 0; r < 3; r++) {
                            bool takeB = (pa > 2) || (pb <= 2 && bv[pb] < av[pa]);
                            if (takeB) { ri[r] = bi[pb]; pb++; }
                            else       { ri[r] = ai[pa]; pa++; }
                        }
                        float d0 = (float)(Kd * fma(-2.0, (double)ts[tok * K1_TP + 0], nx2 + nc2s[0]));
                        float d1 = (float)(Kd * fma(-2.0, (double)ts[tok * K1_TP + 1], nx2 + nc2s[1]));
                        float d2 = (float)(Kd * fma(-2.0, (double)ts[tok * K1_TP + 2], nx2 + nc2s[2]));
                        float w0 = 1.0f / (1.0f + d0);
                        float w1 = 1.0f / (1.0f + d1);
                        float w2 = 1.0f / (1.0f + d2);
                        float z  = w0 + w1 + w2;
                        int b = t0 + tok;
                        g_picked[b * 3 + 0] = ri[0];
                        g_picked[b * 3 + 1] = ri[1];
                        g_picked[b * 3 + 2] = ri[2];
                        g_w[b * 3 + 0] = w0 / z;
                        g_w[b * 3 + 1] = w1 / z;
                        g_w[b * 3 + 2] = w2 / z;
                        g_loc[b * 3 + 0] = atomicAdd(&hist[ri[0]], 1);
                        g_loc[b * 3 + 1] = atomicAdd(&hist[ri[1]], 1);
                        g_loc[b * 3 + 2] = atomicAdd(&hist[ri[2]], 1);
                    }
                }
                __syncthreads();
                if (tid < 64) g_blockhist[task * 64 + tid] = hist[tid];
                __syncthreads();
            } else {
                // -------- W^T build for expert e --------
                int e = task - NBLK;
                float* wsm = sm;                     // [128][132] wsm[k][o]
                const float4* w4 = (const float4*)(W + (size_t)e * DD * DD);
#pragma unroll
                for (int i = 0; i < 8; i++) {
                    int idx = i * NT + tid;
                    float4 v = __ldg(w4 + idx);
                    *(float4*)(wsm + (idx >> 5) * 132 + (idx & 31) * 4) = v;
                }
                __syncthreads();
                float4* dst = (float4*)(g_wt + (size_t)e * DD * DD);
#pragma unroll
                for (int i = 0; i < 8; i++) {
                    int idx = i * NT + tid;
                    int o = idx >> 5, kq = idx & 31;
                    float4 v;
                    v.x = to_tf32(wsm[(kq * 4 + 0) * 132 + o]);
                    v.y = to_tf32(wsm[(kq * 4 + 1) * 132 + o]);
                    v.z = to_tf32(wsm[(kq * 4 + 2) * 132 + o]);
                    v.w = to_tf32(wsm[(kq * 4 + 3) * 132 + o]);
                    dst[o * 32 + kq] = v;
                }
                __syncthreads();
            }
        }
    }

    grid_sync();

    // ================= Phase B: scan (CTA 0) ===================================
    if (cta == 0) {
        int* csum = (int*)sm;        // [256]
        int* cnts = csum + 256;      // [64]
        int* off  = cnts + 64;       // [65]
        int* toff = off + 65;        // [64]
        int e = tid & 63, c = (tid >> 6) & 3;

        if (tid < 256) {
            int s = 0;
#pragma unroll 8
            for (int i = 0; i < 64; i++) s += g_blockhist[((c << 6) + i) * 64 + e];
            csum[c * 64 + e] = s;
        }
        __syncthreads();

        if (tid < 64) {
            int t0 = csum[0 * 64 + tid], t1 = csum[1 * 64 + tid];
            int t2 = csum[2 * 64 + tid], t3 = csum[3 * 64 + tid];
            cnts[tid] = t0 + t1 + t2 + t3;
            csum[0 * 64 + tid] = 0;
            csum[1 * 64 + tid] = t0;
            csum[2 * 64 + tid] = t0 + t1;
            csum[3 * 64 + tid] = t0 + t1 + t2;
        }
        __syncthreads();

        if (tid == 0) {
            int o = 0, to = 0;
            for (int i = 0; i < 64; i++) {
                off[i] = o; toff[i] = to;
                o += cnts[i]; to += (cnts[i] + 63) >> 6;
            }
            off[64] = o; g_ntiles = to;
        }
        __syncthreads();

        if (tid < 64) {
            g_offsets[tid] = off[tid];
            int nt = (cnts[tid] + 63) >> 6;
            for (int i = 0; i < nt; i++)
                g_tiles[toff[tid] + i] = make_int2(tid, off[tid] + (i << 6));
        }
        if (tid == 0) g_offsets[64] = off[64];
        __syncthreads();

        // pass 2 with register prefetch (breaks the serial L2 chain, MLP=16)
        if (tid < 256) {
            int run = off[e] + csum[c * 64 + e];
#pragma unroll
            for (int ch = 0; ch < 4; ch++) {
                int v[16];
#pragma unroll
                for (int i = 0; i < 16; i++)
                    v[i] = g_blockhist[((c << 6) + ch * 16 + i) * 64 + e];
#pragma unroll
                for (int i = 0; i < 16; i++) {
                    g_blockbase[((c << 6) + ch * 16 + i) * 64 + e] = run;
                    run += v[i];
                }
            }
        }
    }

    grid_sync();

    // ================= Phase C: scatter (+ reset g_task_a: phase A is dead) ====
    {
        if (cta == 0 && tid == 0) g_task_a = 0;
        int t = cta * NT + tid;
        if (t < BB) {
            int blk = t >> 6;
#pragma unroll
            for (int j = 0; j < 3; j++) {
                int e = g_picked[t * 3 + j];
                int p = g_blockbase[blk * 64 + e] + g_loc[t * 3 + j];
                g_entry_token[p] = t;
                g_pos[t * 3 + j] = p;
            }
        }
    }

    grid_sync();

    // ================= Phase D: TF32 grouped GEMM, work-stealing ===============
    {
        float* As = sm;                  // [64][K4_LD]
        float* Bs = sm + 64 * K4_LD;     // [128][K4_LD]
        uint32_t bsb = (uint32_t)__cvta_generic_to_shared(Bs);
        int ntiles = g_ntiles;
        const float4* x4 = (const float4*)x;

        for (;;) {
            if (tid == 0) s_task = atomicAdd(&g_task_d, 1);
            __syncthreads();
            int t = s_task;
            __syncthreads();
            if (t >= ntiles) break;

            int2 tl = g_tiles[t];
            int e = tl.x, rs = tl.y;
            int rows = g_offsets[e + 1] - rs;
            if (rows > 64) rows = 64;

            // B: cp.async copy of pre-rounded W^T (4096 float4)
            const float4* wt4 = (const float4*)(g_wt + (size_t)e * DD * DD);
#pragma unroll
            for (int i = 0; i < 8; i++) {
                int idx = i * NT + tid;
                int o = idx >> 5, kq = idx & 31;
                cp_async16(bsb + (o * K4_LD + kq * 4) * 4, wt4 + idx);
            }
            CP_COMMIT();

            // A: gather + tf32 round + STS (8 threads per row)
            {
                int tr = tid >> 3, h = tid & 7;
                bool valid = tr < rows;
                int tok = valid ? g_entry_token[rs + tr] : 0;
                const float4* xr = x4 + (size_t)tok * 32;
#pragma unroll
                for (int i = 0; i < 4; i++) {
                    int kc = h * 4 + i;
                    float4 v = make_float4(0.f, 0.f, 0.f, 0.f);
                    if (valid) v = __ldg(xr + kc);
                    v.x = to_tf32(v.x); v.y = to_tf32(v.y);
                    v.z = to_tf32(v.z); v.w = to_tf32(v.w);
                    *(float4*)(As + tr * K4_LD + kc * 4) = v;
                }
            }
            CP_WAIT0();
            __syncthreads();

            int wid = tid >> 5, lane = tid & 31;
            int gid = lane >> 2, tig = lane & 3;
            int m0 = (wid & 3) * 16, n0 = (wid >> 2) * 32;

            float acc[4][4];
#pragma unroll
            for (int j = 0; j < 4; j++)
#pragma unroll
                for (int r = 0; r < 4; r++) acc[j][r] = 0.f;

            const float* arow = As + (m0 + gid) * K4_LD + tig;
            const float* brow = Bs + (n0 + gid) * K4_LD + tig;

#pragma unroll 4
            for (int kb = 0; kb < 128; kb += 8) {
                uint32_t a[4];
                {
                    const float* p = arow + kb;
                    a[0] = __float_as_uint(p[0]);
                    a[1] = __float_as_uint(p[8 * K4_LD]);
                    a[2] = __float_as_uint(p[4]);
                    a[3] = __float_as_uint(p[8 * K4_LD + 4]);
                }
                uint32_t b[4][2];
#pragma unroll
                for (int j = 0; j < 4; j++) {
                    const float* p = brow + j * 8 * K4_LD + kb;
                    b[j][0] = __float_as_uint(p[0]);
                    b[j][1] = __float_as_uint(p[4]);
                }
#pragma unroll
                for (int j = 0; j < 4; j++)
                    mma_tf32(acc[j], a, b[j]);
            }

            const float* be = bias + (size_t)e * DD;
            {
                int r0 = m0 + gid;
                int r1 = r0 + 8;
                bool v0 = r0 < rows, v1 = r1 < rows;
                float* o0 = g_scratch + (size_t)(rs + r0) * DD;
                float* o1 = g_scratch + (size_t)(rs + r1) * DD;
#pragma unroll
                for (int j = 0; j < 4; j++) {
                    int col = n0 + j * 8 + tig * 2;
                    float2 bv = *(const float2*)(be + col);
                    if (v0) *(float2*)(o0 + col) =
                        make_float2(acc[j][0] + bv.x, acc[j][1] + bv.y);
                    if (v1) *(float2*)(o1 + col) =
                        make_float2(acc[j][2] + bv.x, acc[j][3] + bv.y);
                }
            }
        }
    }

    grid_sync();

    // ================= Phase E: combine (static) + reset g_task_d ==============
    {
        if (cta == 0 && tid == 0) g_task_d = 0;   // phase D is dead now
        int gw = (cta * NT + tid) >> 5;           // global warp id, 0..4735
        int c = (tid & 31) * 4;
        for (int b = gw; b < BB; b += GRID * 16) {
            float4 r = make_float4(0.f, 0.f, 0.f, 0.f);
#pragma unroll
            for (int j = 0; j < 3; j++) {
                float w = g_w[b * 3 + j];
                int   p = g_pos[b * 3 + j];
                float4 sv = *(const float4*)(g_scratch + (size_t)p * DD + c);
                r.x += w * sv.x;
                r.y += w * sv.y;
                r.z += w * sv.z;
                r.w += w * sv.w;
            }
            *(float4*)(out + (size_t)b * DD + c) = r;
        }
    }
    // no final barrier: counters already reset in dead windows; kernel just ends
}

// ---------------- launch ------------------------------------------------------
extern "C" void kernel_launch(void* const* d_in, const int* in_sizes, int n_in,
                              void* d_out, int out_size) {
    const float* x    = (const float*)d_in[0];
    const float* dsc  = (const float*)d_in[1];
    const float* cent = (const float*)d_in[2];
    const float* W    = (const float*)d_in[3];
    const float* bias = (const float*)d_in[4];
    float* out = (float*)d_out;

    cudaFuncSetAttribute(fused, cudaFuncAttributeMaxDynamicSharedMemorySize,
                         FUSED_SMEM);
    fused<<<GRID, NT, FUSED_SMEM>>>(x, dsc, cent, W, bias, out);
}